// round 1
// baseline (speedup 1.0000x reference)
#include <cuda_runtime.h>
#include <math.h>

#define NQ     10
#define DIM    1024      // 2^NQ amplitudes
#define NP     100       // params per branch
#define BATCH  256
#define FD     256
#define NOUT   30

// per-branch expectation values: [branch][batch][30]
__device__ float g_m[3][BATCH][NOUT];

__global__ __launch_bounds__(512) void qsb_circuit(
    const float* __restrict__ x,
    const float* __restrict__ W1, const float* __restrict__ b1, const float* __restrict__ base1,
    const float* __restrict__ W2, const float* __restrict__ b2, const float* __restrict__ base2,
    const float* __restrict__ W3, const float* __restrict__ b3, const float* __restrict__ base3)
{
    const int bt = blockIdx.x;   // batch element
    const int br = blockIdx.y;   // branch 0..2
    const float* __restrict__ W  = (br == 0) ? W1 : (br == 1) ? W2 : W3;
    const float* __restrict__ bb = (br == 0) ? b1 : (br == 1) ? b2 : b3;
    const float* __restrict__ bs = (br == 0) ? base1 : (br == 1) ? base2 : base3;

    __shared__ float xs[FD];       // x row
    __shared__ float pc[NP];       // cos(p/2)
    __shared__ float psn[NP];      // sin(p/2)
    __shared__ float sre[DIM];
    __shared__ float sim[DIM];
    __shared__ float redbuf[48];

    const int tid  = threadIdx.x;        // 0..511
    const int wid  = tid >> 5;
    const int lane = tid & 31;

    // stage x row + init state
    for (int k = tid; k < FD; k += 512) xs[k] = x[bt * FD + k];
    for (int i = tid; i < DIM; i += 512) { sre[i] = (i == 0) ? 1.0f : 0.0f; sim[i] = 0.0f; }
    __syncthreads();

    // params: one warp per param (16 warps round-robin over 100 params)
    for (int j = wid; j < NP; j += 16) {
        const float* __restrict__ wr = W + j * FD;
        float s = 0.0f;
        #pragma unroll
        for (int k = lane; k < FD; k += 32) s = fmaf(xs[k], wr[k], s);
        #pragma unroll
        for (int o = 16; o; o >>= 1) s += __shfl_xor_sync(0xffffffffu, s, o);
        if (lane == 0) {
            float t = s + bb[j] + bs[j];
            float p = 6.283185307179586f / (1.0f + expf(-t));   // sigmoid * 2pi
            float cc, ss;
            sincosf(0.5f * p, &ss, &cc);
            pc[j] = cc; psn[j] = ss;
        }
    }
    __syncthreads();

    int idx = 0;
    #pragma unroll 1
    for (int layer = 0; layer < 2; ++layer) {
        // ---- fused RZ*RY*RX per wire ----
        #pragma unroll 1
        for (int w = 0; w < NQ; ++w) {
            float c1 = pc[idx],     s1 = psn[idx];
            float c2 = pc[idx + 1], s2 = psn[idx + 1];
            float c3 = pc[idx + 2], s3 = psn[idx + 2];
            idx += 3;
            // A = RY * RX
            float A00r =  c2 * c1, A00i =  s2 * s1;
            float A01r = -s2 * c1, A01i = -c2 * s1;
            float A10r =  s2 * c1, A10i = -c2 * s1;
            float A11r =  c2 * c1, A11i = -s2 * s1;
            // U = RZ * A : row0 *= (c3 - i s3), row1 *= (c3 + i s3)
            float U00r = c3 * A00r + s3 * A00i, U00i = c3 * A00i - s3 * A00r;
            float U01r = c3 * A01r + s3 * A01i, U01i = c3 * A01i - s3 * A01r;
            float U10r = c3 * A10r - s3 * A10i, U10i = c3 * A10i + s3 * A10r;
            float U11r = c3 * A11r - s3 * A11i, U11i = c3 * A11i + s3 * A11r;

            int bit = NQ - 1 - w;
            int msk = (1 << bit) - 1;
            int i0  = ((tid >> bit) << (bit + 1)) | (tid & msk);
            int i1  = i0 | (1 << bit);
            float a0r = sre[i0], a0i = sim[i0];
            float a1r = sre[i1], a1i = sim[i1];
            sre[i0] = U00r * a0r - U00i * a0i + U01r * a1r - U01i * a1i;
            sim[i0] = U00r * a0i + U00i * a0r + U01r * a1i + U01i * a1r;
            sre[i1] = U10r * a0r - U10i * a0i + U11r * a1r - U11i * a1i;
            sim[i1] = U10r * a0i + U10i * a0r + U11r * a1i + U11i * a1r;
            __syncthreads();
        }

        // ---- ring CRX, forward: control i, target (i+1)%NQ ----
        #pragma unroll 1
        for (int i = 0; i < NQ; ++i) {
            int c = i, t = (i + 1) % NQ;
            float ct = pc[idx], sn = psn[idx]; idx++;
            int bc = NQ - 1 - c, btb = NQ - 1 - t;
            int blo = bc < btb ? bc : btb;
            int bhi = bc < btb ? btb : bc;
            if (tid < 256) {
                int ix = tid;
                ix = ((ix >> blo) << (blo + 1)) | (ix & ((1 << blo) - 1));
                ix = ((ix >> bhi) << (bhi + 1)) | (ix & ((1 << bhi) - 1));
                int i0 = ix | (1 << bc);          // control=1, target=0
                int i1 = i0 | (1 << btb);         // control=1, target=1
                float a0r = sre[i0], a0i = sim[i0];
                float a1r = sre[i1], a1i = sim[i1];
                sre[i0] = fmaf(ct, a0r,  sn * a1i);
                sim[i0] = fmaf(ct, a0i, -sn * a1r);
                sre[i1] = fmaf(ct, a1r,  sn * a0i);
                sim[i1] = fmaf(ct, a1i, -sn * a0r);
            }
            __syncthreads();
        }

        // ---- ring CRX, backward: control i, target (i-1+NQ)%NQ ----
        #pragma unroll 1
        for (int i = NQ - 1; i >= 0; --i) {
            int c = i, t = (i - 1 + NQ) % NQ;
            float ct = pc[idx], sn = psn[idx]; idx++;
            int bc = NQ - 1 - c, btb = NQ - 1 - t;
            int blo = bc < btb ? bc : btb;
            int bhi = bc < btb ? btb : bc;
            if (tid < 256) {
                int ix = tid;
                ix = ((ix >> blo) << (blo + 1)) | (ix & ((1 << blo) - 1));
                ix = ((ix >> bhi) << (bhi + 1)) | (ix & ((1 << bhi) - 1));
                int i0 = ix | (1 << bc);
                int i1 = i0 | (1 << btb);
                float a0r = sre[i0], a0i = sim[i0];
                float a1r = sre[i1], a1i = sim[i1];
                sre[i0] = fmaf(ct, a0r,  sn * a1i);
                sim[i0] = fmaf(ct, a0i, -sn * a1r);
                sre[i1] = fmaf(ct, a1r,  sn * a0i);
                sim[i1] = fmaf(ct, a1i, -sn * a0r);
            }
            __syncthreads();
        }
    }

    // ---- measurements: X, Y, Z per wire ----
    #pragma unroll 1
    for (int w = 0; w < NQ; ++w) {
        int bit = NQ - 1 - w;
        int msk = (1 << bit) - 1;
        int i0  = ((tid >> bit) << (bit + 1)) | (tid & msk);
        int i1  = i0 | (1 << bit);
        float a0r = sre[i0], a0i = sim[i0];
        float a1r = sre[i1], a1i = sim[i1];
        float xr = a0r * a1r + a0i * a1i;          // Re(conj(a0)*a1)
        float xi = a0r * a1i - a0i * a1r;          // Im(conj(a0)*a1)
        float zd = a0r * a0r + a0i * a0i - a1r * a1r - a1i * a1i;
        #pragma unroll
        for (int o = 16; o; o >>= 1) {
            xr += __shfl_xor_sync(0xffffffffu, xr, o);
            xi += __shfl_xor_sync(0xffffffffu, xi, o);
            zd += __shfl_xor_sync(0xffffffffu, zd, o);
        }
        if (lane == 0) { redbuf[wid] = xr; redbuf[16 + wid] = xi; redbuf[32 + wid] = zd; }
        __syncthreads();
        if (tid == 0) {
            float X = 0.f, Y = 0.f, Z = 0.f;
            #pragma unroll
            for (int k = 0; k < 16; ++k) { X += redbuf[k]; Y += redbuf[16 + k]; Z += redbuf[32 + k]; }
            g_m[br][bt][w]      = 2.0f * X;
            g_m[br][bt][10 + w] = 2.0f * Y;
            g_m[br][bt][20 + w] = Z;
        }
        __syncthreads();
    }
}

__global__ void qsb_combine(
    const float* __restrict__ ar_, const float* __restrict__ ai_,
    const float* __restrict__ br_, const float* __restrict__ bi_,
    const float* __restrict__ gr_, const float* __restrict__ gi_,
    float* __restrict__ out)
{
    int j = blockIdx.x * blockDim.x + threadIdx.x;
    if (j >= BATCH * NOUT) return;
    int b = j / NOUT, k = j % NOUT;
    float ar = ar_[0], ai = ai_[0];
    float brv = br_[0], bi = bi_[0];
    float gr = gr_[0], gi = gi_[0];
    float norm = sqrtf(ar * ar + ai * ai + brv * brv + bi * bi + gr * gr + gi * gi + 1e-9f);
    float m1 = g_m[0][b][k], m2 = g_m[1][b][k], m3 = g_m[2][b][k];
    float re = (ar * m1 + brv * m2 + gr * m3) / norm;
    float im = (ai * m1 + bi * m2 + gi * m3) / norm;
    out[j] = sqrtf(re * re + im * im);
}

extern "C" void kernel_launch(void* const* d_in, const int* in_sizes, int n_in,
                              void* d_out, int out_size)
{
    const float* x     = (const float*)d_in[0];
    const float* W1    = (const float*)d_in[1];
    const float* b1    = (const float*)d_in[2];
    const float* W2    = (const float*)d_in[3];
    const float* b2    = (const float*)d_in[4];
    const float* W3    = (const float*)d_in[5];
    const float* b3    = (const float*)d_in[6];
    const float* base1 = (const float*)d_in[7];
    const float* base2 = (const float*)d_in[8];
    const float* base3 = (const float*)d_in[9];

    dim3 grid(BATCH, 3);
    qsb_circuit<<<grid, 512>>>(x, W1, b1, base1, W2, b2, base2, W3, b3, base3);

    qsb_combine<<<(BATCH * NOUT + 255) / 256, 256>>>(
        (const float*)d_in[10], (const float*)d_in[11],
        (const float*)d_in[12], (const float*)d_in[13],
        (const float*)d_in[14], (const float*)d_in[15],
        (float*)d_out);
}

// round 2
// speedup vs baseline: 1.1917x; 1.1917x over previous
#include <cuda_runtime.h>
#include <math.h>

#define NQ     10
#define DIM    1024
#define NP     100
#define BATCH  256
#define FD     256
#define NOUT   30

// per-branch expectation values: [branch][batch][30]
__device__ float g_m[3][BATCH][NOUT];

// ---------------- register-resident gate helpers ----------------
// amplitude index = lane*32 + m : bits 0..4 = register index m, bits 5..9 = lane bits

template<int B>
__device__ __forceinline__ void apply1q(float* vr, float* vi, int lane,
    float U00r, float U00i, float U01r, float U01i,
    float U10r, float U10i, float U11r, float U11i)
{
    if constexpr (B < 5) {
        constexpr int st = 1 << B;
        #pragma unroll
        for (int q = 0; q < 16; ++q) {
            const int m0 = ((q >> B) << (B + 1)) | (q & (st - 1));
            const int m1 = m0 | st;
            float a0r = vr[m0], a0i = vi[m0], a1r = vr[m1], a1i = vi[m1];
            vr[m0] = U00r*a0r - U00i*a0i + U01r*a1r - U01i*a1i;
            vi[m0] = U00r*a0i + U00i*a0r + U01r*a1i + U01i*a1r;
            vr[m1] = U10r*a0r - U10i*a0i + U11r*a1r - U11i*a1i;
            vi[m1] = U10r*a0i + U10i*a0r + U11r*a1i + U11i*a1r;
        }
    } else {
        constexpr int lm = 1 << (B - 5);
        const bool r = (lane & lm) != 0;
        // r==0: new = U00*mine + U01*partner ; r==1: new = U11*mine + U10*partner
        float cmr = r ? U11r : U00r, cmi = r ? U11i : U00i;
        float cpr = r ? U10r : U01r, cpi = r ? U10i : U01i;
        #pragma unroll
        for (int m = 0; m < 32; ++m) {
            float pr = __shfl_xor_sync(0xffffffffu, vr[m], lm);
            float pi = __shfl_xor_sync(0xffffffffu, vi[m], lm);
            float mr = vr[m], mi = vi[m];
            vr[m] = cmr*mr - cmi*mi + cpr*pr - cpi*pi;
            vi[m] = cmr*mi + cmi*mr + cpr*pi + cpi*pr;
        }
    }
}

// controlled-RX on (control bit BC, target bit BT); RX = [[c, -is],[-is, c]]
// symmetric: new_mine_r = c*mine_r + s*partner_i ; new_mine_i = c*mine_i - s*partner_r
template<int BC, int BT>
__device__ __forceinline__ void applycrx(float* vr, float* vi, int lane, float c, float s)
{
    if constexpr (BT < 5) {
        constexpr int tm = 1 << BT;
        if constexpr (BC < 5) {
            #pragma unroll
            for (int m0 = 0; m0 < 32; ++m0) {
                if ((m0 & (1 << BC)) && !(m0 & tm)) {
                    const int m1 = m0 | tm;
                    float a0r = vr[m0], a0i = vi[m0], a1r = vr[m1], a1i = vi[m1];
                    vr[m0] = c*a0r + s*a1i;
                    vi[m0] = c*a0i - s*a1r;
                    vr[m1] = c*a1r + s*a0i;
                    vi[m1] = c*a1i - s*a0r;
                }
            }
        } else {
            if (lane & (1 << (BC - 5))) {
                #pragma unroll
                for (int q = 0; q < 16; ++q) {
                    const int m0 = ((q >> BT) << (BT + 1)) | (q & (tm - 1));
                    const int m1 = m0 | tm;
                    float a0r = vr[m0], a0i = vi[m0], a1r = vr[m1], a1i = vi[m1];
                    vr[m0] = c*a0r + s*a1i;
                    vi[m0] = c*a0i - s*a1r;
                    vr[m1] = c*a1r + s*a0i;
                    vi[m1] = c*a1i - s*a0r;
                }
            }
        }
    } else {
        constexpr int lm = 1 << (BT - 5);
        if constexpr (BC < 5) {
            #pragma unroll
            for (int m = 0; m < 32; ++m) {
                if (m & (1 << BC)) {
                    float pr = __shfl_xor_sync(0xffffffffu, vr[m], lm);
                    float pi = __shfl_xor_sync(0xffffffffu, vi[m], lm);
                    float mr = vr[m], mi = vi[m];
                    vr[m] = c*mr + s*pi;
                    vi[m] = c*mi - s*pr;
                }
            }
        } else {
            const bool ctrl = (lane & (1 << (BC - 5))) != 0;
            #pragma unroll
            for (int m = 0; m < 32; ++m) {
                float pr = __shfl_xor_sync(0xffffffffu, vr[m], lm);
                float pi = __shfl_xor_sync(0xffffffffu, vi[m], lm);
                float mr = vr[m], mi = vi[m];
                float nr = c*mr + s*pi;
                float ni = c*mi - s*pr;
                vr[m] = ctrl ? nr : mr;
                vi[m] = ctrl ? ni : mi;
            }
        }
    }
}

template<int B>
__device__ __forceinline__ void measure(const float* vr, const float* vi, int lane,
                                        float& X, float& Y, float& Z)
{
    float zr = 0.f, zi = 0.f, zd = 0.f;
    if constexpr (B < 5) {
        constexpr int st = 1 << B;
        #pragma unroll
        for (int q = 0; q < 16; ++q) {
            const int m0 = ((q >> B) << (B + 1)) | (q & (st - 1));
            const int m1 = m0 | st;
            zr += vr[m0]*vr[m1] + vi[m0]*vi[m1];
            zi += vr[m0]*vi[m1] - vi[m0]*vr[m1];
            zd += vr[m0]*vr[m0] + vi[m0]*vi[m0] - vr[m1]*vr[m1] - vi[m1]*vi[m1];
        }
        #pragma unroll
        for (int o = 16; o; o >>= 1) {
            zr += __shfl_xor_sync(0xffffffffu, zr, o);
            zi += __shfl_xor_sync(0xffffffffu, zi, o);
            zd += __shfl_xor_sync(0xffffffffu, zd, o);
        }
        X = 2.f*zr; Y = 2.f*zi; Z = zd;
    } else {
        constexpr int lm = 1 << (B - 5);
        const float sgn = (lane & lm) ? -1.f : 1.f;
        #pragma unroll
        for (int m = 0; m < 32; ++m) {
            float pr = __shfl_xor_sync(0xffffffffu, vr[m], lm);
            float pi = __shfl_xor_sync(0xffffffffu, vi[m], lm);
            float mr = vr[m], mi = vi[m];
            zr += mr*pr + mi*pi;      // both lanes of a pair compute equal values -> 2x
            zi += mr*pi - mi*pr;      // sign-flipped on r=1 lanes, fixed below
            zd += mr*mr + mi*mi;      // |mine|^2, signed below
        }
        zi *= sgn; zd *= sgn;
        #pragma unroll
        for (int o = 16; o; o >>= 1) {
            zr += __shfl_xor_sync(0xffffffffu, zr, o);
            zi += __shfl_xor_sync(0xffffffffu, zi, o);
            zd += __shfl_xor_sync(0xffffffffu, zd, o);
        }
        // pair sums are double-counted (both lanes), so 2*Re(z01) == zr_total
        X = zr; Y = zi; Z = zd;
    }
}

// ---------------- main circuit kernel: one warp per (batch, branch) ----------------
__global__ void __launch_bounds__(32) qsb_circuit(
    const float* __restrict__ x,
    const float* __restrict__ W1, const float* __restrict__ b1, const float* __restrict__ base1,
    const float* __restrict__ W2, const float* __restrict__ b2, const float* __restrict__ base2,
    const float* __restrict__ W3, const float* __restrict__ b3, const float* __restrict__ base3)
{
    const int bid = blockIdx.x;        // 0..767
    const int br  = bid >> 8;          // branch
    const int bt  = bid & 255;         // batch element
    const float* __restrict__ W  = (br == 0) ? W1 : (br == 1) ? W2 : W3;
    const float* __restrict__ bb = (br == 0) ? b1 : (br == 1) ? b2 : b3;
    const float* __restrict__ bs = (br == 0) ? base1 : (br == 1) ? base2 : base3;
    const int lane = threadIdx.x;

    __shared__ float spc[NP];
    __shared__ float sps[NP];

    // x row cached in registers (8 floats per lane)
    const float4* x4 = (const float4*)(x + bt * FD);
    const float4 xa = x4[lane];
    const float4 xb = x4[lane + 32];

    // params: warp-cooperative dot products, sincos broadcast via per-warp smem
    #pragma unroll 2
    for (int j = 0; j < NP; ++j) {
        const float4* w4 = (const float4*)(W + j * FD);
        float4 wa = w4[lane];
        float4 wb = w4[lane + 32];
        float s = xa.x*wa.x + xa.y*wa.y + xa.z*wa.z + xa.w*wa.w
                + xb.x*wb.x + xb.y*wb.y + xb.z*wb.z + xb.w*wb.w;
        #pragma unroll
        for (int o = 16; o; o >>= 1) s += __shfl_xor_sync(0xffffffffu, s, o);
        float t = s + bb[j] + bs[j];
        float half = 3.14159265358979f / (1.0f + __expf(-t));  // (sigmoid*2pi)/2
        float cc, sn;
        __sincosf(half, &sn, &cc);
        if (lane == 0) { spc[j] = cc; sps[j] = sn; }
    }
    __syncwarp();

    // statevector in registers: |0...0>
    float vr[32], vi[32];
    #pragma unroll
    for (int m = 0; m < 32; ++m) { vr[m] = 0.f; vi[m] = 0.f; }
    vr[0] = (lane == 0) ? 1.0f : 0.0f;

    int idx = 0;
    #define FUSED(B) { \
        float c1 = spc[idx], s1 = sps[idx]; \
        float c2 = spc[idx+1], s2 = sps[idx+1]; \
        float c3 = spc[idx+2], s3 = sps[idx+2]; idx += 3; \
        float A00r =  c2*c1, A00i =  s2*s1; \
        float A01r = -s2*c1, A01i = -c2*s1; \
        float A10r =  s2*c1, A10i = -c2*s1; \
        float A11r =  c2*c1, A11i = -s2*s1; \
        apply1q<B>(vr, vi, lane, \
            c3*A00r + s3*A00i, c3*A00i - s3*A00r, \
            c3*A01r + s3*A01i, c3*A01i - s3*A01r, \
            c3*A10r - s3*A10i, c3*A10i + s3*A10r, \
            c3*A11r - s3*A11i, c3*A11i + s3*A11r); }

    #define CRX(BC,BT) { float c = spc[idx], s = sps[idx]; idx++; \
        applycrx<BC,BT>(vr, vi, lane, c, s); }

    #pragma unroll 1
    for (int layer = 0; layer < 2; ++layer) {
        // fused RZ*RY*RX per wire 0..9 (wire w -> bit 9-w)
        FUSED(9) FUSED(8) FUSED(7) FUSED(6) FUSED(5)
        FUSED(4) FUSED(3) FUSED(2) FUSED(1) FUSED(0)
        // forward ring: control i, target (i+1)%10
        CRX(9,8) CRX(8,7) CRX(7,6) CRX(6,5) CRX(5,4)
        CRX(4,3) CRX(3,2) CRX(2,1) CRX(1,0) CRX(0,9)
        // backward ring: i=9..0, control i, target (i-1)%10
        CRX(0,1) CRX(1,2) CRX(2,3) CRX(3,4) CRX(4,5)
        CRX(5,6) CRX(6,7) CRX(7,8) CRX(8,9) CRX(9,0)
    }

    #define MEAS(w) { float X, Y, Z; measure<9-(w)>(vr, vi, lane, X, Y, Z); \
        if (lane == 0) { g_m[br][bt][w] = X; g_m[br][bt][10+(w)] = Y; g_m[br][bt][20+(w)] = Z; } }

    MEAS(0) MEAS(1) MEAS(2) MEAS(3) MEAS(4)
    MEAS(5) MEAS(6) MEAS(7) MEAS(8) MEAS(9)
}

// ---------------- superposition combine ----------------
__global__ void qsb_combine(
    const float* __restrict__ ar_, const float* __restrict__ ai_,
    const float* __restrict__ br_, const float* __restrict__ bi_,
    const float* __restrict__ gr_, const float* __restrict__ gi_,
    float* __restrict__ out)
{
    int j = blockIdx.x * blockDim.x + threadIdx.x;
    if (j >= BATCH * NOUT) return;
    int b = j / NOUT, k = j % NOUT;
    float ar = ar_[0], ai = ai_[0];
    float brv = br_[0], bi = bi_[0];
    float gr = gr_[0], gi = gi_[0];
    float norm = sqrtf(ar*ar + ai*ai + brv*brv + bi*bi + gr*gr + gi*gi + 1e-9f);
    float m1 = g_m[0][b][k], m2 = g_m[1][b][k], m3 = g_m[2][b][k];
    float re = (ar * m1 + brv * m2 + gr * m3) / norm;
    float im = (ai * m1 + bi * m2 + gi * m3) / norm;
    out[j] = sqrtf(re * re + im * im);
}

extern "C" void kernel_launch(void* const* d_in, const int* in_sizes, int n_in,
                              void* d_out, int out_size)
{
    const float* x     = (const float*)d_in[0];
    const float* W1    = (const float*)d_in[1];
    const float* b1    = (const float*)d_in[2];
    const float* W2    = (const float*)d_in[3];
    const float* b2    = (const float*)d_in[4];
    const float* W3    = (const float*)d_in[5];
    const float* b3    = (const float*)d_in[6];
    const float* base1 = (const float*)d_in[7];
    const float* base2 = (const float*)d_in[8];
    const float* base3 = (const float*)d_in[9];

    qsb_circuit<<<3 * BATCH, 32>>>(x, W1, b1, base1, W2, b2, base2, W3, b3, base3);

    qsb_combine<<<(BATCH * NOUT + 255) / 256, 256>>>(
        (const float*)d_in[10], (const float*)d_in[11],
        (const float*)d_in[12], (const float*)d_in[13],
        (const float*)d_in[14], (const float*)d_in[15],
        (float*)d_out);
}

// round 4
// speedup vs baseline: 1.5098x; 1.2669x over previous
#include <cuda_runtime.h>
#include <math.h>

#define NQ     10
#define NP     100
#define BATCH  256
#define FD     256
#define NOUT   30

// pairwise warp barrier for circuit c (ids 1..3, 64 threads each)
__device__ __forceinline__ void barpair(int c) {
    asm volatile("bar.sync %0, 64;" :: "r"(c + 1) : "memory");
}

__device__ __forceinline__ float wred(float v) {
    #pragma unroll
    for (int o = 16; o; o >>= 1) v += __shfl_xor_sync(0xffffffffu, v, o);
    return v;
}

// ---------------- gate helpers ----------------
// amplitude index: bits 0..3 = reg index m, bits 4..8 = lane bits, bit 9 = warp half

template<int B>
__device__ __forceinline__ void apply1q(float* vr, float* vi, int lane,
    float U00r, float U00i, float U01r, float U01i,
    float U10r, float U10i, float U11r, float U11i)
{
    if constexpr (B < 4) {
        constexpr int st = 1 << B;
        #pragma unroll
        for (int q = 0; q < 8; ++q) {
            const int m0 = ((q >> B) << (B + 1)) | (q & (st - 1));
            const int m1 = m0 | st;
            float a0r = vr[m0], a0i = vi[m0], a1r = vr[m1], a1i = vi[m1];
            vr[m0] = U00r*a0r - U00i*a0i + U01r*a1r - U01i*a1i;
            vi[m0] = U00r*a0i + U00i*a0r + U01r*a1i + U01i*a1r;
            vr[m1] = U10r*a0r - U10i*a0i + U11r*a1r - U11i*a1i;
            vi[m1] = U10r*a0i + U10i*a0r + U11r*a1i + U11i*a1r;
        }
    } else {
        constexpr int lm = 1 << (B - 4);
        const bool r = (lane & lm) != 0;
        float cmr = r ? U11r : U00r, cmi = r ? U11i : U00i;
        float cpr = r ? U10r : U01r, cpi = r ? U10i : U01i;
        #pragma unroll
        for (int m = 0; m < 16; ++m) {
            float pr = __shfl_xor_sync(0xffffffffu, vr[m], lm);
            float pi = __shfl_xor_sync(0xffffffffu, vi[m], lm);
            float mr = vr[m], mi = vi[m];
            vr[m] = cmr*mr - cmi*mi + cpr*pr - cpi*pi;
            vi[m] = cmr*mi + cmi*mr + cpr*pi + cpi*pr;
        }
    }
}

// 1q gate on bit 9 (cross-warp, smem exchange)
__device__ __forceinline__ void apply1q9(float* vr, float* vi, int cc_, int t6,
    float (*bufr)[64], float (*bufi)[64],
    float U00r, float U00i, float U01r, float U01i,
    float U10r, float U10i, float U11r, float U11i)
{
    const int h = t6 >> 5;
    float cmr = h ? U11r : U00r, cmi = h ? U11i : U00i;
    float cpr = h ? U10r : U01r, cpi = h ? U10i : U01i;
    barpair(cc_);
    #pragma unroll
    for (int m = 0; m < 16; ++m) { bufr[m][t6] = vr[m]; bufi[m][t6] = vi[m]; }
    barpair(cc_);
    const int p = t6 ^ 32;
    #pragma unroll
    for (int m = 0; m < 16; ++m) {
        float pr = bufr[m][p], pi = bufi[m][p];
        float mr = vr[m], mi = vi[m];
        vr[m] = cmr*mr - cmi*mi + cpr*pr - cpi*pi;
        vi[m] = cmr*mi + cmi*mr + cpr*pi + cpi*pr;
    }
}

// controlled-RX on (control bit BC, target bit BT), BT <= 8
template<int BC, int BT>
__device__ __forceinline__ void applycrx(float* vr, float* vi, int lane, int t6, float cg, float sg)
{
    if constexpr (BT < 4) {
        constexpr int tm = 1 << BT;
        if constexpr (BC < 4) {
            #pragma unroll
            for (int m0 = 0; m0 < 16; ++m0)
                if ((m0 & (1 << BC)) && !(m0 & tm)) {
                    const int m1 = m0 | tm;
                    float a0r = vr[m0], a0i = vi[m0], a1r = vr[m1], a1i = vi[m1];
                    vr[m0] = cg*a0r + sg*a1i; vi[m0] = cg*a0i - sg*a1r;
                    vr[m1] = cg*a1r + sg*a0i; vi[m1] = cg*a1i - sg*a0r;
                }
        } else if constexpr (BC < 9) {
            if (lane & (1 << (BC - 4))) {
                #pragma unroll
                for (int q = 0; q < 8; ++q) {
                    const int m0 = ((q >> BT) << (BT + 1)) | (q & (tm - 1));
                    const int m1 = m0 | tm;
                    float a0r = vr[m0], a0i = vi[m0], a1r = vr[m1], a1i = vi[m1];
                    vr[m0] = cg*a0r + sg*a1i; vi[m0] = cg*a0i - sg*a1r;
                    vr[m1] = cg*a1r + sg*a0i; vi[m1] = cg*a1i - sg*a0r;
                }
            }
        } else { // control = bit 9 (upper warp only)
            if (t6 & 32) {
                #pragma unroll
                for (int q = 0; q < 8; ++q) {
                    const int m0 = ((q >> BT) << (BT + 1)) | (q & (tm - 1));
                    const int m1 = m0 | tm;
                    float a0r = vr[m0], a0i = vi[m0], a1r = vr[m1], a1i = vi[m1];
                    vr[m0] = cg*a0r + sg*a1i; vi[m0] = cg*a0i - sg*a1r;
                    vr[m1] = cg*a1r + sg*a0i; vi[m1] = cg*a1i - sg*a0r;
                }
            }
        }
    } else { // 4 <= BT <= 8 : shfl target
        constexpr int lm = 1 << (BT - 4);
        if constexpr (BC < 4) {
            #pragma unroll
            for (int m = 0; m < 16; ++m)
                if (m & (1 << BC)) {
                    float pr = __shfl_xor_sync(0xffffffffu, vr[m], lm);
                    float pi = __shfl_xor_sync(0xffffffffu, vi[m], lm);
                    float mr = vr[m], mi = vi[m];
                    vr[m] = cg*mr + sg*pi; vi[m] = cg*mi - sg*pr;
                }
        } else if constexpr (BC < 9) {
            const bool ctrl = (lane & (1 << (BC - 4))) != 0;
            #pragma unroll
            for (int m = 0; m < 16; ++m) {
                float pr = __shfl_xor_sync(0xffffffffu, vr[m], lm);
                float pi = __shfl_xor_sync(0xffffffffu, vi[m], lm);
                float mr = vr[m], mi = vi[m];
                float nr = cg*mr + sg*pi, ni = cg*mi - sg*pr;
                vr[m] = ctrl ? nr : mr; vi[m] = ctrl ? ni : mi;
            }
        } else { // control = bit 9 (upper warp only, warp-uniform)
            if (t6 & 32) {
                #pragma unroll
                for (int m = 0; m < 16; ++m) {
                    float pr = __shfl_xor_sync(0xffffffffu, vr[m], lm);
                    float pi = __shfl_xor_sync(0xffffffffu, vi[m], lm);
                    float mr = vr[m], mi = vi[m];
                    vr[m] = cg*mr + sg*pi; vi[m] = cg*mi - sg*pr;
                }
            }
        }
    }
}

// controlled-RX with target = bit 9 (cross-warp exchange); BC < 9
template<int BC>
__device__ __forceinline__ void applycrx9(float* vr, float* vi, int cc_, int t6,
    float (*bufr)[64], float (*bufi)[64], float cg, float sg)
{
    const int lane = t6 & 31;
    bool act;
    if constexpr (BC < 4) act = true;
    else act = (lane & (1 << (BC - 4))) != 0;   // partner has same lane bits -> same act
    barpair(cc_);
    if (act) {
        #pragma unroll
        for (int m = 0; m < 16; ++m) { bufr[m][t6] = vr[m]; bufi[m][t6] = vi[m]; }
    }
    barpair(cc_);
    if (act) {
        const int p = t6 ^ 32;
        #pragma unroll
        for (int m = 0; m < 16; ++m) {
            if constexpr (BC < 4) { if (!(m & (1 << BC))) continue; }
            float pr = bufr[m][p], pi = bufi[m][p];
            float mr = vr[m], mi = vi[m];
            vr[m] = cg*mr + sg*pi; vi[m] = cg*mi - sg*pr;
        }
    }
}

// measurements: per-warp partials; sum of both halves = (X, Y, Z)
template<int B>
__device__ __forceinline__ void measure(const float* vr, const float* vi, int lane,
                                        float& X, float& Y, float& Z)
{
    float zr = 0.f, zi = 0.f, zd = 0.f;
    if constexpr (B < 4) {
        constexpr int st = 1 << B;
        #pragma unroll
        for (int q = 0; q < 8; ++q) {
            const int m0 = ((q >> B) << (B + 1)) | (q & (st - 1));
            const int m1 = m0 | st;
            zr += vr[m0]*vr[m1] + vi[m0]*vi[m1];
            zi += vr[m0]*vi[m1] - vi[m0]*vr[m1];
            zd += vr[m0]*vr[m0] + vi[m0]*vi[m0] - vr[m1]*vr[m1] - vi[m1]*vi[m1];
        }
        X = 2.f * wred(zr); Y = 2.f * wred(zi); Z = wred(zd);
    } else {
        constexpr int lm = 1 << (B - 4);
        const float sgn = (lane & lm) ? -1.f : 1.f;
        #pragma unroll
        for (int m = 0; m < 16; ++m) {
            float pr = __shfl_xor_sync(0xffffffffu, vr[m], lm);
            float pi = __shfl_xor_sync(0xffffffffu, vi[m], lm);
            float mr = vr[m], mi = vi[m];
            zr += mr*pr + mi*pi;
            zi += mr*pi - mi*pr;
            zd += mr*mr + mi*mi;
        }
        X = wred(zr); Y = wred(zi * sgn); Z = wred(zd * sgn);
    }
}

__device__ __forceinline__ void measure9(const float* vr, const float* vi, int cc_, int t6,
    float (*bufr)[64], float (*bufi)[64], float& X, float& Y, float& Z)
{
    barpair(cc_);
    #pragma unroll
    for (int m = 0; m < 16; ++m) { bufr[m][t6] = vr[m]; bufi[m][t6] = vi[m]; }
    barpair(cc_);
    const int p = t6 ^ 32;
    const float sgn = (t6 & 32) ? -1.f : 1.f;
    float zr = 0.f, zi = 0.f, zd = 0.f;
    #pragma unroll
    for (int m = 0; m < 16; ++m) {
        float pr = bufr[m][p], pi = bufi[m][p];
        float mr = vr[m], mi = vi[m];
        zr += mr*pr + mi*pi;
        zi += mr*pi - mi*pr;
        zd += mr*mr + mi*mi;
    }
    X = wred(zr); Y = wred(zi * sgn); Z = wred(zd * sgn);
}

// ---------------- fused kernel: one block per batch element ----------------
// block = 192 threads = 3 circuits (branches) x 2 warps
__global__ void __launch_bounds__(192) qsb_fused(
    const float* __restrict__ x,
    const float* __restrict__ W1, const float* __restrict__ b1, const float* __restrict__ base1,
    const float* __restrict__ W2, const float* __restrict__ b2, const float* __restrict__ base2,
    const float* __restrict__ W3, const float* __restrict__ b3, const float* __restrict__ base3,
    const float* __restrict__ ar_, const float* __restrict__ ai_,
    const float* __restrict__ br_, const float* __restrict__ bi_,
    const float* __restrict__ gr_, const float* __restrict__ gi_,
    float* __restrict__ out)
{
    const int bt   = blockIdx.x;
    const int tid  = threadIdx.x;
    const int lane = tid & 31;

    __shared__ float spc[3 * NP];
    __shared__ float sps[3 * NP];
    __shared__ float exr[3][16][64];
    __shared__ float exi[3][16][64];
    __shared__ float mpart[3][2][NOUT];

    // ---- param stage: 6 warps x 50 dot products over 300 params ----
    {
        const int wi = tid >> 5;
        const float4* x4 = (const float4*)(x + bt * FD);
        const float4 xa = x4[lane];
        const float4 xb = x4[lane + 32];
        #pragma unroll 2
        for (int jj = wi; jj < 3 * NP; jj += 6) {
            const int br2 = (jj < NP) ? 0 : ((jj < 2 * NP) ? 1 : 2);
            const int j = jj - br2 * NP;
            const float* __restrict__ W  = (br2 == 0) ? W1 : (br2 == 1) ? W2 : W3;
            const float* __restrict__ bb = (br2 == 0) ? b1 : (br2 == 1) ? b2 : b3;
            const float* __restrict__ bs = (br2 == 0) ? base1 : (br2 == 1) ? base2 : base3;
            const float4* w4 = (const float4*)(W + j * FD);
            float4 wa = w4[lane];
            float4 wb = w4[lane + 32];
            float s0 = xa.x*wa.x + xa.y*wa.y + xa.z*wa.z + xa.w*wa.w;
            float s1 = xb.x*wb.x + xb.y*wb.y + xb.z*wb.z + xb.w*wb.w;
            float s = wred(s0 + s1);
            float t = s + bb[j] + bs[j];
            float half = 3.14159265358979f / (1.0f + __expf(-t));   // (sigmoid*2pi)/2
            float cc2, sn2;
            __sincosf(half, &sn2, &cc2);
            if (lane == 0) { spc[jj] = cc2; sps[jj] = sn2; }
        }
    }
    __syncthreads();

    // ---- circuit stage ----
    const int cc_ = tid / 64;      // circuit / branch
    const int t6  = tid & 63;
    const int h   = t6 >> 5;
    const float* __restrict__ pcB = &spc[cc_ * NP];
    const float* __restrict__ psB = &sps[cc_ * NP];
    float (*bufr)[64] = exr[cc_];
    float (*bufi)[64] = exi[cc_];

    float vr[16], vi[16];
    #pragma unroll
    for (int m = 0; m < 16; ++m) { vr[m] = 0.f; vi[m] = 0.f; }
    if (t6 == 0) vr[0] = 1.0f;

    int idx = 0;

    #define UCOEF \
        float c1 = pcB[idx], s1 = psB[idx]; \
        float c2 = pcB[idx+1], s2 = psB[idx+1]; \
        float c3 = pcB[idx+2], s3 = psB[idx+2]; idx += 3; \
        float A00r =  c2*c1, A00i =  s2*s1; \
        float A01r = -s2*c1, A01i = -c2*s1; \
        float A10r =  s2*c1, A10i = -c2*s1; \
        float A11r =  c2*c1, A11i = -s2*s1; \
        float U00r = c3*A00r + s3*A00i, U00i = c3*A00i - s3*A00r; \
        float U01r = c3*A01r + s3*A01i, U01i = c3*A01i - s3*A01r; \
        float U10r = c3*A10r - s3*A10i, U10i = c3*A10i + s3*A10r; \
        float U11r = c3*A11r - s3*A11i, U11i = c3*A11i + s3*A11r;

    #define FUSED(B) { UCOEF \
        apply1q<B>(vr, vi, lane, U00r,U00i,U01r,U01i,U10r,U10i,U11r,U11i); }
    #define FUSED9() { UCOEF \
        apply1q9(vr, vi, cc_, t6, bufr, bufi, U00r,U00i,U01r,U01i,U10r,U10i,U11r,U11i); }
    #define CRX(BC,BT) { float cg = pcB[idx], sg = psB[idx]; idx++; \
        applycrx<BC,BT>(vr, vi, lane, t6, cg, sg); }
    #define CRX9(BC) { float cg = pcB[idx], sg = psB[idx]; idx++; \
        applycrx9<BC>(vr, vi, cc_, t6, bufr, bufi, cg, sg); }

    #pragma unroll 1
    for (int layer = 0; layer < 2; ++layer) {
        // fused RZ*RY*RX per wire 0..9 (wire w -> bit 9-w)
        FUSED9() FUSED(8) FUSED(7) FUSED(6) FUSED(5)
        FUSED(4) FUSED(3) FUSED(2) FUSED(1) FUSED(0)
        // forward ring (bit-space): control, target
        CRX(9,8) CRX(8,7) CRX(7,6) CRX(6,5) CRX(5,4)
        CRX(4,3) CRX(3,2) CRX(2,1) CRX(1,0) CRX9(0)
        // backward ring
        CRX(0,1) CRX(1,2) CRX(2,3) CRX(3,4) CRX(4,5)
        CRX(5,6) CRX(6,7) CRX(7,8) CRX9(8)  CRX(9,0)
    }

    // ---- measurements ----
    {   // wire 0 = bit 9 (cross-warp)
        float X, Y, Z;
        measure9(vr, vi, cc_, t6, bufr, bufi, X, Y, Z);
        if (lane == 0) { mpart[cc_][h][0] = X; mpart[cc_][h][10] = Y; mpart[cc_][h][20] = Z; }
    }
    #define MEAS(w) { float X, Y, Z; measure<9-(w)>(vr, vi, lane, X, Y, Z); \
        if (lane == 0) { mpart[cc_][h][w] = X; mpart[cc_][h][10+(w)] = Y; mpart[cc_][h][20+(w)] = Z; } }
    MEAS(1) MEAS(2) MEAS(3) MEAS(4)
    MEAS(5) MEAS(6) MEAS(7) MEAS(8) MEAS(9)

    // ---- combine ----
    __syncthreads();
    if (tid < NOUT) {
        const int k = tid;
        float m1 = mpart[0][0][k] + mpart[0][1][k];
        float m2 = mpart[1][0][k] + mpart[1][1][k];
        float m3 = mpart[2][0][k] + mpart[2][1][k];
        float ar = ar_[0], ai = ai_[0];
        float brv = br_[0], bi = bi_[0];
        float gr = gr_[0], gi = gi_[0];
        float norm = sqrtf(ar*ar + ai*ai + brv*brv + bi*bi + gr*gr + gi*gi + 1e-9f);
        float re = (ar * m1 + brv * m2 + gr * m3) / norm;
        float im = (ai * m1 + bi * m2 + gi * m3) / norm;
        out[bt * NOUT + k] = sqrtf(re * re + im * im);
    }
}

extern "C" void kernel_launch(void* const* d_in, const int* in_sizes, int n_in,
                              void* d_out, int out_size)
{
    // d_in order: x, W1, b1, W2, b2, W3, b3, base1, base2, base3, ar, ai, br, bi, gr, gi
    qsb_fused<<<BATCH, 192>>>(
        (const float*)d_in[0],
        (const float*)d_in[1], (const float*)d_in[2], (const float*)d_in[7],   // W1, b1, base1
        (const float*)d_in[3], (const float*)d_in[4], (const float*)d_in[8],   // W2, b2, base2
        (const float*)d_in[5], (const float*)d_in[6], (const float*)d_in[9],   // W3, b3, base3
        (const float*)d_in[10], (const float*)d_in[11],
        (const float*)d_in[12], (const float*)d_in[13],
        (const float*)d_in[14], (const float*)d_in[15],
        (float*)d_out);
}

// round 5
// speedup vs baseline: 1.6805x; 1.1131x over previous
#include <cuda_runtime.h>
#include <math.h>

#define NP     100
#define BATCH  256
#define FD     256
#define NOUT   30

// barrier over one circuit's 4 warps (128 threads), ids 1..3
__device__ __forceinline__ void barc(int c) {
    asm volatile("bar.sync %0, 128;" :: "r"(c + 1) : "memory");
}

__device__ __forceinline__ float wred(float v) {
    #pragma unroll
    for (int o = 16; o; o >>= 1) v += __shfl_xor_sync(0xffffffffu, v, o);
    return v;
}

// ---------------- gate helpers ----------------
// amplitude index: bits 0..2 = reg index m, bits 3..7 = lane bits, bits 8..9 = warp index

template<int B>   // B in 0..7
__device__ __forceinline__ void apply1q(float* vr, float* vi, int lane,
    float U00r, float U00i, float U01r, float U01i,
    float U10r, float U10i, float U11r, float U11i)
{
    if constexpr (B < 3) {
        constexpr int st = 1 << B;
        #pragma unroll
        for (int q = 0; q < 4; ++q) {
            const int m0 = ((q >> B) << (B + 1)) | (q & (st - 1));
            const int m1 = m0 | st;
            float a0r = vr[m0], a0i = vi[m0], a1r = vr[m1], a1i = vi[m1];
            vr[m0] = U00r*a0r - U00i*a0i + U01r*a1r - U01i*a1i;
            vi[m0] = U00r*a0i + U00i*a0r + U01r*a1i + U01i*a1r;
            vr[m1] = U10r*a0r - U10i*a0i + U11r*a1r - U11i*a1i;
            vi[m1] = U10r*a0i + U10i*a0r + U11r*a1i + U11i*a1r;
        }
    } else {
        constexpr int lm = 1 << (B - 3);
        const bool r = (lane & lm) != 0;
        float cmr = r ? U11r : U00r, cmi = r ? U11i : U00i;
        float cpr = r ? U10r : U01r, cpi = r ? U10i : U01i;
        #pragma unroll
        for (int m = 0; m < 8; ++m) {
            float pr = __shfl_xor_sync(0xffffffffu, vr[m], lm);
            float pi = __shfl_xor_sync(0xffffffffu, vi[m], lm);
            float mr = vr[m], mi = vi[m];
            vr[m] = cmr*mr - cmi*mi + cpr*pr - cpi*pi;
            vi[m] = cmr*mi + cmi*mr + cpr*pi + cpi*pr;
        }
    }
}

// 1q gate on warp bit (WB = 1 -> bit8, WB = 2 -> bit9), cross-warp smem exchange
template<int WB>
__device__ __forceinline__ void apply1qW(float* vr, float* vi, int cc, int t7,
    float (*bufr)[128], float (*bufi)[128],
    float U00r, float U00i, float U01r, float U01i,
    float U10r, float U10i, float U11r, float U11i)
{
    const bool hi = ((t7 >> 5) & WB) != 0;
    float cmr = hi ? U11r : U00r, cmi = hi ? U11i : U00i;
    float cpr = hi ? U10r : U01r, cpi = hi ? U10i : U01i;
    barc(cc);
    #pragma unroll
    for (int m = 0; m < 8; ++m) { bufr[m][t7] = vr[m]; bufi[m][t7] = vi[m]; }
    barc(cc);
    const int p = t7 ^ (WB << 5);
    #pragma unroll
    for (int m = 0; m < 8; ++m) {
        float pr = bufr[m][p], pi = bufi[m][p];
        float mr = vr[m], mi = vi[m];
        vr[m] = cmr*mr - cmi*mi + cpr*pr - cpi*pi;
        vi[m] = cmr*mi + cmi*mr + cpr*pi + cpi*pr;
    }
}

// controlled-RX, target bit BT <= 7, control BC anywhere (0..9)
template<int BC, int BT>
__device__ __forceinline__ void applycrx(float* vr, float* vi, int lane, int t7, float cg, float sg)
{
    bool act = true;
    if constexpr (BC >= 8)      act = ((t7 >> 5) & (1 << (BC - 8))) != 0;
    else if constexpr (BC >= 3) act = (lane & (1 << (BC - 3))) != 0;

    if constexpr (BT < 3) {
        constexpr int tm = 1 << BT;
        if constexpr (BC < 3) {
            #pragma unroll
            for (int m0 = 0; m0 < 8; ++m0)
                if ((m0 & (1 << BC)) && !(m0 & tm)) {
                    const int m1 = m0 | tm;
                    float a0r = vr[m0], a0i = vi[m0], a1r = vr[m1], a1i = vi[m1];
                    vr[m0] = cg*a0r + sg*a1i; vi[m0] = cg*a0i - sg*a1r;
                    vr[m1] = cg*a1r + sg*a0i; vi[m1] = cg*a1i - sg*a0r;
                }
        } else {
            if (act) {
                #pragma unroll
                for (int q = 0; q < 4; ++q) {
                    const int m0 = ((q >> BT) << (BT + 1)) | (q & (tm - 1));
                    const int m1 = m0 | tm;
                    float a0r = vr[m0], a0i = vi[m0], a1r = vr[m1], a1i = vi[m1];
                    vr[m0] = cg*a0r + sg*a1i; vi[m0] = cg*a0i - sg*a1r;
                    vr[m1] = cg*a1r + sg*a0i; vi[m1] = cg*a1i - sg*a0r;
                }
            }
        }
    } else {
        constexpr int lm = 1 << (BT - 3);
        if constexpr (BC < 3) {
            #pragma unroll
            for (int m = 0; m < 8; ++m)
                if (m & (1 << BC)) {
                    float pr = __shfl_xor_sync(0xffffffffu, vr[m], lm);
                    float pi = __shfl_xor_sync(0xffffffffu, vi[m], lm);
                    float mr = vr[m], mi = vi[m];
                    vr[m] = cg*mr + sg*pi; vi[m] = cg*mi - sg*pr;
                }
        } else if constexpr (BC >= 8) {
            if (act) {   // warp-uniform
                #pragma unroll
                for (int m = 0; m < 8; ++m) {
                    float pr = __shfl_xor_sync(0xffffffffu, vr[m], lm);
                    float pi = __shfl_xor_sync(0xffffffffu, vi[m], lm);
                    float mr = vr[m], mi = vi[m];
                    vr[m] = cg*mr + sg*pi; vi[m] = cg*mi - sg*pr;
                }
            }
        } else {
            #pragma unroll
            for (int m = 0; m < 8; ++m) {
                float pr = __shfl_xor_sync(0xffffffffu, vr[m], lm);
                float pi = __shfl_xor_sync(0xffffffffu, vi[m], lm);
                float mr = vr[m], mi = vi[m];
                float nr = cg*mr + sg*pi, ni = cg*mi - sg*pr;
                vr[m] = act ? nr : mr; vi[m] = act ? ni : mi;
            }
        }
    }
}

// controlled-RX with target = warp bit WB; RM = reg mask for control in reg bits (0 = all regs)
template<int WB, int RM>
__device__ __forceinline__ void applycrxW(float* vr, float* vi, int cc, int t7,
    float (*bufr)[128], float (*bufi)[128], float cg, float sg, bool act)
{
    barc(cc);
    if (act) {
        #pragma unroll
        for (int m = 0; m < 8; ++m) {
            if constexpr (RM != 0) { if (!(m & RM)) continue; }
            bufr[m][t7] = vr[m]; bufi[m][t7] = vi[m];
        }
    }
    barc(cc);
    if (act) {
        const int p = t7 ^ (WB << 5);
        #pragma unroll
        for (int m = 0; m < 8; ++m) {
            if constexpr (RM != 0) { if (!(m & RM)) continue; }
            float pr = bufr[m][p], pi = bufi[m][p];
            float mr = vr[m], mi = vi[m];
            vr[m] = cg*mr + sg*pi; vi[m] = cg*mi - sg*pr;
        }
    }
}

// ---------------- measurements (per-warp partials; total = sum over 4 warps) ----------------
template<int B>  // B 0..7
__device__ __forceinline__ void measure(const float* vr, const float* vi, int lane,
                                        float& X, float& Y, float& Z)
{
    float zr = 0.f, zi = 0.f, zd = 0.f;
    if constexpr (B < 3) {
        constexpr int st = 1 << B;
        #pragma unroll
        for (int q = 0; q < 4; ++q) {
            const int m0 = ((q >> B) << (B + 1)) | (q & (st - 1));
            const int m1 = m0 | st;
            zr += vr[m0]*vr[m1] + vi[m0]*vi[m1];
            zi += vr[m0]*vi[m1] - vi[m0]*vr[m1];
            zd += vr[m0]*vr[m0] + vi[m0]*vi[m0] - vr[m1]*vr[m1] - vi[m1]*vi[m1];
        }
        X = 2.f * wred(zr); Y = 2.f * wred(zi); Z = wred(zd);
    } else {
        constexpr int lm = 1 << (B - 3);
        const float sgn = (lane & lm) ? -1.f : 1.f;
        #pragma unroll
        for (int m = 0; m < 8; ++m) {
            float pr = __shfl_xor_sync(0xffffffffu, vr[m], lm);
            float pi = __shfl_xor_sync(0xffffffffu, vi[m], lm);
            float mr = vr[m], mi = vi[m];
            zr += mr*pr + mi*pi;
            zi += mr*pi - mi*pr;
            zd += mr*mr + mi*mi;
        }
        X = wred(zr); Y = wred(zi * sgn); Z = wred(zd * sgn);
    }
}

template<int WB>
__device__ __forceinline__ void measureW(const float* vr, const float* vi, int cc, int t7,
    float (*bufr)[128], float (*bufi)[128], float& X, float& Y, float& Z)
{
    barc(cc);
    #pragma unroll
    for (int m = 0; m < 8; ++m) { bufr[m][t7] = vr[m]; bufi[m][t7] = vi[m]; }
    barc(cc);
    const int p = t7 ^ (WB << 5);
    const float sgn = ((t7 >> 5) & WB) ? -1.f : 1.f;
    float zr = 0.f, zi = 0.f, zd = 0.f;
    #pragma unroll
    for (int m = 0; m < 8; ++m) {
        float pr = bufr[m][p], pi = bufi[m][p];
        float mr = vr[m], mi = vi[m];
        zr += mr*pr + mi*pi;
        zi += mr*pi - mi*pr;
        zd += mr*mr + mi*mi;
    }
    X = wred(zr); Y = wred(zi * sgn); Z = wred(zd * sgn);
}

// ---------------- fused kernel: one block per batch element ----------------
// block = 384 threads = 3 circuits (branches) x 4 warps
__global__ void __launch_bounds__(384) qsb_fused(
    const float* __restrict__ x,
    const float* __restrict__ W1, const float* __restrict__ b1, const float* __restrict__ base1,
    const float* __restrict__ W2, const float* __restrict__ b2, const float* __restrict__ base2,
    const float* __restrict__ W3, const float* __restrict__ b3, const float* __restrict__ base3,
    const float* __restrict__ ar_, const float* __restrict__ ai_,
    const float* __restrict__ br_, const float* __restrict__ bi_,
    const float* __restrict__ gr_, const float* __restrict__ gi_,
    float* __restrict__ out)
{
    const int bt   = blockIdx.x;
    const int tid  = threadIdx.x;
    const int lane = tid & 31;

    __shared__ __align__(16) float xs[FD];
    __shared__ float spc[3 * NP];
    __shared__ float sps[3 * NP];
    __shared__ float exr[3][8][128];
    __shared__ float exi[3][8][128];
    __shared__ float mpart[3][4][NOUT];

    // ---- stage x row ----
    for (int k = tid; k < FD; k += 384) xs[k] = x[bt * FD + k];
    __syncthreads();

    // ---- params: one thread per param (300 of 384 threads), no shuffle chains ----
    if (tid < 3 * NP) {
        const int br2 = (tid < NP) ? 0 : ((tid < 2 * NP) ? 1 : 2);
        const int j = tid - br2 * NP;
        const float* __restrict__ W  = (br2 == 0) ? W1 : (br2 == 1) ? W2 : W3;
        const float* __restrict__ bb = (br2 == 0) ? b1 : (br2 == 1) ? b2 : b3;
        const float* __restrict__ bs = (br2 == 0) ? base1 : (br2 == 1) ? base2 : base3;
        const float4* __restrict__ w4 = (const float4*)(W + j * FD);
        const float4* __restrict__ x4 = (const float4*)xs;
        float a0 = 0.f, a1 = 0.f, a2 = 0.f, a3 = 0.f;
        #pragma unroll
        for (int k = 0; k < 64; k += 4) {
            float4 wv0 = w4[k],   xv0 = x4[k];
            float4 wv1 = w4[k+1], xv1 = x4[k+1];
            float4 wv2 = w4[k+2], xv2 = x4[k+2];
            float4 wv3 = w4[k+3], xv3 = x4[k+3];
            a0 = fmaf(wv0.x, xv0.x, fmaf(wv0.y, xv0.y, fmaf(wv0.z, xv0.z, fmaf(wv0.w, xv0.w, a0))));
            a1 = fmaf(wv1.x, xv1.x, fmaf(wv1.y, xv1.y, fmaf(wv1.z, xv1.z, fmaf(wv1.w, xv1.w, a1))));
            a2 = fmaf(wv2.x, xv2.x, fmaf(wv2.y, xv2.y, fmaf(wv2.z, xv2.z, fmaf(wv2.w, xv2.w, a2))));
            a3 = fmaf(wv3.x, xv3.x, fmaf(wv3.y, xv3.y, fmaf(wv3.z, xv3.z, fmaf(wv3.w, xv3.w, a3))));
        }
        float s = (a0 + a1) + (a2 + a3);
        float t = s + bb[j] + bs[j];
        float half = 3.14159265358979f / (1.0f + __expf(-t));   // (sigmoid*2pi)/2
        float cc2, sn2;
        __sincosf(half, &sn2, &cc2);
        spc[tid] = cc2; sps[tid] = sn2;
    }
    __syncthreads();

    // ---- circuit stage ----
    const int cc = tid >> 7;      // circuit / branch (0..2)
    const int t7 = tid & 127;
    const int w  = t7 >> 5;       // warp within circuit (bits 8,9)
    const float* __restrict__ pcB = &spc[cc * NP];
    const float* __restrict__ psB = &sps[cc * NP];
    float (*bufr)[128] = exr[cc];
    float (*bufi)[128] = exi[cc];

    float vr[8], vi[8];
    #pragma unroll
    for (int m = 0; m < 8; ++m) { vr[m] = 0.f; vi[m] = 0.f; }
    if (t7 == 0) vr[0] = 1.0f;

    int idx = 0;

    #define UCOEF \
        float c1 = pcB[idx], s1 = psB[idx]; \
        float c2 = pcB[idx+1], s2 = psB[idx+1]; \
        float c3 = pcB[idx+2], s3 = psB[idx+2]; idx += 3; \
        float A00r =  c2*c1, A00i =  s2*s1; \
        float A01r = -s2*c1, A01i = -c2*s1; \
        float A10r =  s2*c1, A10i = -c2*s1; \
        float A11r =  c2*c1, A11i = -s2*s1; \
        float U00r = c3*A00r + s3*A00i, U00i = c3*A00i - s3*A00r; \
        float U01r = c3*A01r + s3*A01i, U01i = c3*A01i - s3*A01r; \
        float U10r = c3*A10r - s3*A10i, U10i = c3*A10i + s3*A10r; \
        float U11r = c3*A11r - s3*A11i, U11i = c3*A11i + s3*A11r;

    #define FUSED(B) { UCOEF \
        apply1q<B>(vr, vi, lane, U00r,U00i,U01r,U01i,U10r,U10i,U11r,U11i); }
    #define FUSEDW(WB) { UCOEF \
        apply1qW<WB>(vr, vi, cc, t7, bufr, bufi, U00r,U00i,U01r,U01i,U10r,U10i,U11r,U11i); }
    #define CRX(BC,BT) { float cg = pcB[idx], sg = psB[idx]; idx++; \
        applycrx<BC,BT>(vr, vi, lane, t7, cg, sg); }
    #define CRXW(WB,RM,ACT) { float cg = pcB[idx], sg = psB[idx]; idx++; \
        applycrxW<WB,RM>(vr, vi, cc, t7, bufr, bufi, cg, sg, (ACT)); }

    #pragma unroll 1
    for (int layer = 0; layer < 2; ++layer) {
        // fused RZ*RY*RX per wire 0..9 (wire v -> bit 9-v)
        FUSEDW(2) FUSEDW(1)
        FUSED(7) FUSED(6) FUSED(5) FUSED(4)
        FUSED(3) FUSED(2) FUSED(1) FUSED(0)
        // forward ring (bit space): (9,8)(8,7)(7,6)(6,5)(5,4)(4,3)(3,2)(2,1)(1,0)(0,9)
        CRXW(1, 0, (w & 2) != 0)                 // control bit9, target bit8
        CRX(8,7) CRX(7,6) CRX(6,5) CRX(5,4)
        CRX(4,3) CRX(3,2) CRX(2,1) CRX(1,0)
        CRXW(2, 1, true)                          // control reg bit0, target bit9
        // backward ring: (0,1)(1,2)(2,3)(3,4)(4,5)(5,6)(6,7)(7,8)(8,9)(9,0)
        CRX(0,1) CRX(1,2) CRX(2,3) CRX(3,4)
        CRX(4,5) CRX(5,6) CRX(6,7)
        CRXW(1, 0, (lane & 16) != 0)              // control bit7 (lane), target bit8
        CRXW(2, 0, (w & 1) != 0)                  // control bit8, target bit9
        CRX(9,0)                                  // control bit9 (warp), target reg bit0
    }

    // ---- measurements (wire v -> bit 9-v) ----
    {
        float X, Y, Z;
        measureW<2>(vr, vi, cc, t7, bufr, bufi, X, Y, Z);   // wire 0
        if (lane == 0) { mpart[cc][w][0] = X; mpart[cc][w][10] = Y; mpart[cc][w][20] = Z; }
    }
    {
        float X, Y, Z;
        measureW<1>(vr, vi, cc, t7, bufr, bufi, X, Y, Z);   // wire 1
        if (lane == 0) { mpart[cc][w][1] = X; mpart[cc][w][11] = Y; mpart[cc][w][21] = Z; }
    }
    #define MEAS(v) { float X, Y, Z; measure<9-(v)>(vr, vi, lane, X, Y, Z); \
        if (lane == 0) { mpart[cc][w][v] = X; mpart[cc][w][10+(v)] = Y; mpart[cc][w][20+(v)] = Z; } }
    MEAS(2) MEAS(3) MEAS(4) MEAS(5) MEAS(6) MEAS(7) MEAS(8) MEAS(9)

    // ---- combine ----
    __syncthreads();
    if (tid < NOUT) {
        const int k = tid;
        float m1 = (mpart[0][0][k] + mpart[0][1][k]) + (mpart[0][2][k] + mpart[0][3][k]);
        float m2 = (mpart[1][0][k] + mpart[1][1][k]) + (mpart[1][2][k] + mpart[1][3][k]);
        float m3 = (mpart[2][0][k] + mpart[2][1][k]) + (mpart[2][2][k] + mpart[2][3][k]);
        float ar = ar_[0], ai = ai_[0];
        float brv = br_[0], bi = bi_[0];
        float gr = gr_[0], gi = gi_[0];
        float norm = sqrtf(ar*ar + ai*ai + brv*brv + bi*bi + gr*gr + gi*gi + 1e-9f);
        float re = (ar * m1 + brv * m2 + gr * m3) / norm;
        float im = (ai * m1 + bi * m2 + gi * m3) / norm;
        out[bt * NOUT + k] = sqrtf(re * re + im * im);
    }
}

extern "C" void kernel_launch(void* const* d_in, const int* in_sizes, int n_in,
                              void* d_out, int out_size)
{
    // d_in order: x, W1, b1, W2, b2, W3, b3, base1, base2, base3, ar, ai, br, bi, gr, gi
    qsb_fused<<<BATCH, 384>>>(
        (const float*)d_in[0],
        (const float*)d_in[1], (const float*)d_in[2], (const float*)d_in[7],
        (const float*)d_in[3], (const float*)d_in[4], (const float*)d_in[8],
        (const float*)d_in[5], (const float*)d_in[6], (const float*)d_in[9],
        (const float*)d_in[10], (const float*)d_in[11],
        (const float*)d_in[12], (const float*)d_in[13],
        (const float*)d_in[14], (const float*)d_in[15],
        (float*)d_out);
}